// round 15
// baseline (speedup 1.0000x reference)
#include <cuda_runtime.h>
#include <cuda_fp16.h>
#include <cstdint>

// ---------------------------------------------------------------------------
// S5 SSM: ys = 2*Re( scan(Lam_bar, B_bar@u) @ C^T ) + d*u
// R14: chunk-end scan fused into GEMM1 epilogue (smem transpose + 64-step
//      local scans), prep_params merged into prep_weights. GEMM core
//      unchanged from R13 (mma.sync fp16 floor, ~62.6us).
// Pipeline: prep_weights -> convert -> gemm1(+ends) -> carry -> rescan -> gemm2
// ---------------------------------------------------------------------------

#define L_SEQ   32768
#define H_FEAT  512
#define P_STATE 256
#define N2      512
#define C_CHUNKS 512
#define T_CHUNK  64
#define SQ_POW   6

#define BM 128
#define BN 128
#define NCH 16             // 512 / 32
#define ROWB 80            // padded smem row bytes (64B data + 16B pad)
#define OP_BYTES (128 * ROWB)          // 10240 per operand tile
#define STG_BYTES (2 * OP_BYTES)       // A, B
#define NSTAGE 3
#define STAGES_BYTES (NSTAGE * STG_BYTES)   // 61440
#define XP 65                               // transpose pitch (u32)
#define XPOSE_BYTES (128 * XP * 4)          // 33280
#define SMEMB (STAGES_BYTES + XPOSE_BYTES)  // 94720

// Scratch (static __device__; no cudaMalloc allowed)
__device__ uint32_t g_BuH[L_SEQ * P_STATE];            // 32 MB, half2 (re,im)
__device__ __half g_Ah[L_SEQ * N2];                    // 32 MB (u, then xs)
__device__ __half g_W1h[N2 * H_FEAT];
__device__ __half g_W2h[H_FEAT * N2];
__device__ float2 g_a[P_STATE];
__device__ float2 g_aT[P_STATE];
__device__ float2 g_end[C_CHUNKS * P_STATE];
__device__ float2 g_carry[C_CHUNKS * P_STATE];

__device__ __forceinline__ float2 cmul(float2 a, float2 b) {
    return make_float2(a.x * b.x - a.y * b.y, a.x * b.y + a.y * b.x);
}

__device__ __forceinline__ uint32_t smem_u32(const void* p) {
    uint32_t a;
    asm("{ .reg .u64 t; cvta.to.shared.u64 t, %1; cvt.u32.u64 %0, t; }"
        : "=r"(a) : "l"(p));
    return a;
}
__device__ __forceinline__ void cp16(uint32_t dst, const void* src) {
    asm volatile("cp.async.cg.shared.global [%0], [%1], 16;" :: "r"(dst), "l"(src));
}
__device__ __forceinline__ void ldsm4(uint32_t* r, uint32_t addr) {
    asm volatile("ldmatrix.sync.aligned.m8n8.x4.shared.b16 {%0,%1,%2,%3}, [%4];"
                 : "=r"(r[0]), "=r"(r[1]), "=r"(r[2]), "=r"(r[3]) : "r"(addr));
}
__device__ __forceinline__ void mma_f32(float* d, const uint32_t* a,
                                        uint32_t b0, uint32_t b1) {
    asm volatile(
        "mma.sync.aligned.m16n8k16.row.col.f32.f16.f16.f32 "
        "{%0,%1,%2,%3}, {%4,%5,%6,%7}, {%8,%9}, {%0,%1,%2,%3};"
        : "+f"(d[0]), "+f"(d[1]), "+f"(d[2]), "+f"(d[3])
        : "r"(a[0]), "r"(a[1]), "r"(a[2]), "r"(a[3]), "r"(b0), "r"(b1));
}

// ---------------------------------------------------------------------------
// Discretization params + fp16 weights (prep_params merged in; every thread
// of block p recomputes the cheap per-p discretization, thread 0 publishes)
// ---------------------------------------------------------------------------
__global__ void prep_weights(const float* __restrict__ lr,
                             const float* __restrict__ li,
                             const float* __restrict__ delta,
                             const float* __restrict__ b,
                             const float* __restrict__ c) {
    int p = blockIdx.x;        // 0..255
    int h = threadIdx.x;       // 0..511
    float step = expf(delta[p]);
    float hs = 0.5f * step;
    float dr = 1.0f - hs * lr[p];
    float di = -hs * li[p];
    float inv = 1.0f / (dr * dr + di * di);
    float2 BL = make_float2(dr * inv, -di * inv);
    float2 num = make_float2(1.0f + hs * lr[p], hs * li[p]);
    float2 a = cmul(BL, num);
    float2 bs = make_float2(BL.x * step, BL.y * step);
    if (h == 0) {
        g_a[p] = a;
        float2 t = a;
        #pragma unroll
        for (int i = 0; i < SQ_POW; i++) t = cmul(t, t);
        g_aT[p] = t;
    }
    float br = b[(p * H_FEAT + h) * 2 + 0];
    float bi = b[(p * H_FEAT + h) * 2 + 1];
    // W1 as [n=2p|2p+1][k=h]  (mma B operand: [N][K], K contiguous)
    g_W1h[(2 * p) * H_FEAT + h]     = __float2half_rn(bs.x * br - bs.y * bi);
    g_W1h[(2 * p + 1) * H_FEAT + h] = __float2half_rn(bs.x * bi + bs.y * br);
    // W2 as [n=h][k=2p|2p+1]
    g_W2h[h * N2 + 2 * p]     = __float2half_rn( 2.0f * c[(h * P_STATE + p) * 2 + 0]);
    g_W2h[h * N2 + 2 * p + 1] = __float2half_rn(-2.0f * c[(h * P_STATE + p) * 2 + 1]);
}

// fp32 -> fp16 (grid-stride, float4 -> uint2)
__global__ void convert_half(const float4* __restrict__ src,
                             uint2* __restrict__ dst, int n4) {
    int stride = gridDim.x * blockDim.x;
    for (int i = blockIdx.x * blockDim.x + threadIdx.x; i < n4; i += stride) {
        float4 v = src[i];
        __half2 h0 = __floats2half2_rn(v.x, v.y);
        __half2 h1 = __floats2half2_rn(v.z, v.w);
        dst[i] = make_uint2(*(uint32_t*)&h0, *(uint32_t*)&h1);
    }
}

// ---------------------------------------------------------------------------
// fp16 GEMM: C[M,512] = A[M,K] x B[N,K]^T (single-rounded fp16, f32 accum)
// block 128x128, 256 thr, warp 32x64, K-chunks 32, 3-stage cp.async
// MODE 0: write half2 -> g_BuH, then fused chunk-end scan -> g_end
// MODE 1: fp32 out + d*u epilogue
// ---------------------------------------------------------------------------
template <int MODE>
__global__ void __launch_bounds__(256, 1)
gemm_fp16(const __half* __restrict__ Ah, const __half* __restrict__ Bw,
          float* __restrict__ Cout, const float* __restrict__ U,
          const float* __restrict__ D) {
    extern __shared__ char smem[];
    const uint32_t sb = smem_u32(smem);
    const int tid = threadIdx.x;
    const int wid = tid >> 5, lane = tid & 31;
    const int warpM = wid & 3, warpN = wid >> 2;       // 4x2 warp grid
    const int bm = blockIdx.y * BM;
    const int bn = blockIdx.x * BN;

    const char* baseA = (const char*)Ah + (size_t)bm * 1024;
    const char* baseB = (const char*)Bw + (size_t)bn * 1024;

    auto load_chunk = [&](int kt, int st) {
        const uint32_t base = sb + st * STG_BYTES;
        const int kb = kt * 64;                        // byte offset into row
        const int s = tid & 3;
        #pragma unroll
        for (int j = 0; j < 4; j++) {
            const int op = j >> 1;
            const int r = (tid >> 2) + ((j & 1) << 6);
            cp16(base + op * OP_BYTES + r * ROWB + s * 16,
                 (op ? baseB : baseA) + (size_t)r * 1024 + kb + s * 16);
        }
        asm volatile("cp.async.commit_group;");
    };

    load_chunk(0, 0);
    load_chunk(1, 1);

    float acc[2][8][4];
    #pragma unroll
    for (int im = 0; im < 2; im++)
        #pragma unroll
        for (int in = 0; in < 8; in++)
            #pragma unroll
            for (int q = 0; q < 4; q++) acc[im][in][q] = 0.0f;

    const uint32_t a_lo = (lane & 15) * ROWB + (lane >> 4) * 16;
    const uint32_t b_lo = ((lane & 7) + ((lane >> 4) << 3)) * ROWB +
                          ((lane >> 3) & 1) * 16;

    for (int kt = 0; kt < NCH; kt++) {
        const int st = kt % NSTAGE;
        if (kt == NCH - 1) asm volatile("cp.async.wait_group 0;");
        else               asm volatile("cp.async.wait_group 1;");
        __syncthreads();
        if (kt + 2 < NCH) load_chunk(kt + 2, (kt + 2) % NSTAGE);

        const uint32_t sg = sb + st * STG_BYTES;
        #pragma unroll
        for (int ks = 0; ks < 2; ks++) {
            const uint32_t ksb = ks * 32;
            uint32_t ah[2][4], bh[4][4];
            #pragma unroll
            for (int im = 0; im < 2; im++) {
                const uint32_t ao = (warpM * 32 + im * 16) * ROWB + a_lo + ksb;
                ldsm4(ah[im], sg + ao);
            }
            #pragma unroll
            for (int ip = 0; ip < 4; ip++) {
                const uint32_t bo = (warpN * 64 + ip * 16) * ROWB + b_lo + ksb;
                ldsm4(bh[ip], sg + OP_BYTES + bo);
            }
            #pragma unroll
            for (int im = 0; im < 2; im++)
                #pragma unroll
                for (int ip = 0; ip < 4; ip++) {
                    mma_f32(acc[im][2 * ip],     ah[im], bh[ip][0], bh[ip][1]);
                    mma_f32(acc[im][2 * ip + 1], ah[im], bh[ip][2], bh[ip][3]);
                }
        }
    }

    if constexpr (MODE == 0) {
        // Epilogue: write Bu (half2) to gmem AND to smem transpose buffer,
        // then run the 2 chunk-local scans (64 states each) in this block.
        uint32_t* xb = (uint32_t*)(smem + STAGES_BYTES);
        #pragma unroll
        for (int im = 0; im < 2; im++) {
            const int r0 = warpM * 32 + im * 16 + (lane >> 2);   // local row
            #pragma unroll
            for (int in = 0; in < 8; in++) {
                const int pl = warpN * 32 + in * 4 + (lane & 3); // local state
                __half2 h0 = __floats2half2_rn(acc[im][in][0], acc[im][in][1]);
                __half2 h1 = __floats2half2_rn(acc[im][in][2], acc[im][in][3]);
                g_BuH[(size_t)(bm + r0) * P_STATE + (bn >> 1) + pl]     = *(uint32_t*)&h0;
                g_BuH[(size_t)(bm + r0 + 8) * P_STATE + (bn >> 1) + pl] = *(uint32_t*)&h1;
                xb[r0 * XP + pl]       = *(uint32_t*)&h0;
                xb[(r0 + 8) * XP + pl] = *(uint32_t*)&h1;
            }
        }
        __syncthreads();
        if (tid < 128) {
            const int pl = tid & 63;            // local state
            const int chi = tid >> 6;           // which of the 2 chunks
            const int p = (bn >> 1) + pl;
            const float2 a = g_a[p];
            float2 x = make_float2(0.0f, 0.0f);
            const uint32_t* row = xb + (chi * 64) * XP + pl;
            #pragma unroll 8
            for (int t = 0; t < T_CHUNK; t++) {
                uint32_t w = row[t * XP];
                float2 v = __half22float2(*(__half2*)&w);
                float xr = fmaf(a.x, x.x, fmaf(-a.y, x.y, v.x));
                float xi = fmaf(a.x, x.y, fmaf(a.y, x.x, v.y));
                x = make_float2(xr, xi);
            }
            g_end[(bm / T_CHUNK + chi) * P_STATE + p] = x;
        }
    } else {
        #pragma unroll
        for (int im = 0; im < 2; im++) {
            const int row0 = bm + warpM * 32 + im * 16 + (lane >> 2);
            #pragma unroll
            for (int in = 0; in < 8; in++) {
                const int col = bn + warpN * 64 + in * 8 + (lane & 3) * 2;
                float2 v0 = make_float2(acc[im][in][0], acc[im][in][1]);
                float2 v1 = make_float2(acc[im][in][2], acc[im][in][3]);
                float2 dv = *(const float2*)&D[col];
                float2 u0 = *(const float2*)&U[(size_t)row0 * H_FEAT + col];
                float2 u1 = *(const float2*)&U[(size_t)(row0 + 8) * H_FEAT + col];
                v0.x = fmaf(dv.x, u0.x, v0.x); v0.y = fmaf(dv.y, u0.y, v0.y);
                v1.x = fmaf(dv.x, u1.x, v1.x); v1.y = fmaf(dv.y, u1.y, v1.y);
                *(float2*)&Cout[(size_t)row0 * H_FEAT + col] = v0;
                *(float2*)&Cout[(size_t)(row0 + 8) * H_FEAT + col] = v1;
            }
        }
    }
}

// ---------------------------------------------------------------------------
// Kogge-Stone inclusive scan of chunk ends; g_carry[c] = state entering c
// ---------------------------------------------------------------------------
__global__ void __launch_bounds__(C_CHUNKS) carry_kernel() {
    __shared__ float2 s[C_CHUNKS];
    const int p = blockIdx.x;
    const int c = threadIdx.x;
    const float2 aT = g_aT[p];
    s[c] = g_end[c * P_STATE + p];
    float2 m = aT;
    __syncthreads();
    for (int d = 1; d < C_CHUNKS; d <<= 1) {
        float2 other = make_float2(0.0f, 0.0f);
        if (c >= d) other = s[c - d];
        __syncthreads();
        if (c >= d) {
            float2 cur = s[c];
            s[c] = make_float2(cur.x + m.x * other.x - m.y * other.y,
                               cur.y + m.x * other.y + m.y * other.x);
        }
        m = cmul(m, m);
        __syncthreads();
    }
    float2 ci = make_float2(0.0f, 0.0f);
    if (c > 0) ci = s[c - 1];
    g_carry[c * P_STATE + p] = ci;
}

// Rescan with carry init; write fp16 states to g_Ah
__global__ void __launch_bounds__(256) rescan_convert_kernel() {
    const int p = threadIdx.x;
    const int c = blockIdx.x;
    const float2 a = g_a[p];
    float2 x = g_carry[c * P_STATE + p];             // state entering chunk c
    const size_t base = (size_t)c * T_CHUNK * P_STATE + p;
    uint32_t* hi = (uint32_t*)g_Ah;
    #pragma unroll 4
    for (int t = 0; t < T_CHUNK; t++) {
        uint32_t w = g_BuH[base + (size_t)t * P_STATE];
        float2 v = __half22float2(*(__half2*)&w);
        float xr = fmaf(a.x, x.x, fmaf(-a.y, x.y, v.x));
        float xi = fmaf(a.x, x.y, fmaf(a.y, x.x, v.y));
        x = make_float2(xr, xi);
        __half2 h = __floats2half2_rn(x.x, x.y);
        hi[base + (size_t)t * P_STATE] = *(uint32_t*)&h;   // idx == l*256 + p
    }
}

// ---------------------------------------------------------------------------
extern "C" void kernel_launch(void* const* d_in, const int* in_sizes, int n_in,
                              void* d_out, int out_size) {
    const float* u     = (const float*)d_in[0];
    const float* lr    = (const float*)d_in[1];
    const float* li    = (const float*)d_in[2];
    const float* b     = (const float*)d_in[3];
    const float* c     = (const float*)d_in[4];
    const float* d     = (const float*)d_in[5];
    const float* delta = (const float*)d_in[6];
    float* out = (float*)d_out;

    __half* ah;        cudaGetSymbolAddress((void**)&ah, g_Ah);
    __half* w1h;       cudaGetSymbolAddress((void**)&w1h, g_W1h);
    __half* w2h;       cudaGetSymbolAddress((void**)&w2h, g_W2h);

    cudaFuncSetAttribute(gemm_fp16<0>, cudaFuncAttributeMaxDynamicSharedMemorySize, SMEMB);
    cudaFuncSetAttribute(gemm_fp16<1>, cudaFuncAttributeMaxDynamicSharedMemorySize, SMEMB);

    const int N4 = L_SEQ * N2 / 4;

    prep_weights<<<P_STATE, H_FEAT>>>(lr, li, delta, b, c);
    convert_half<<<2048, 256>>>((const float4*)u, (uint2*)ah, N4);
    gemm_fp16<0><<<dim3(N2 / BN, L_SEQ / BM), 256, SMEMB>>>(
        ah, w1h, nullptr, nullptr, nullptr);
    carry_kernel<<<P_STATE, C_CHUNKS>>>();
    rescan_convert_kernel<<<C_CHUNKS, P_STATE>>>();
    gemm_fp16<1><<<dim3(H_FEAT / BN, L_SEQ / BM), 256, SMEMB>>>(
        ah, w2h, out, u, d);
}

// round 16
// speedup vs baseline: 1.1355x; 1.1355x over previous
#include <cuda_runtime.h>
#include <cuda_fp16.h>
#include <cstdint>

// ---------------------------------------------------------------------------
// S5 SSM: ys = 2*Re( scan(Lam_bar, B_bar@u) @ C^T ) + d*u
// R16: R13 skeleton (R14 epilogue-fused scan regressed: tail serialization).
//  + prep_weights and convert_half merged into one launch (block partition)
//  + rescan writes xs in place to g_BuH; g_Ah keeps u fp16; GEMM2 epilogue
//    reads u as fp16 (-32MB fp32 traffic)
// Pipeline: prep+convert -> gemm1 -> ends -> carry -> rescan -> gemm2
// ---------------------------------------------------------------------------

#define L_SEQ   32768
#define H_FEAT  512
#define P_STATE 256
#define N2      512
#define C_CHUNKS 512
#define T_CHUNK  64
#define SQ_POW   6

#define BM 128
#define BN 128
#define NCH 16             // 512 / 32
#define ROWB 80            // padded smem row bytes (64B data + 16B pad)
#define OP_BYTES (128 * ROWB)          // 10240 per operand tile
#define STG_BYTES (2 * OP_BYTES)       // A, B
#define NSTAGE 3
#define SMEMB (NSTAGE * STG_BYTES)     // 61440

// Scratch (static __device__; no cudaMalloc allowed)
__device__ uint32_t g_BuH[L_SEQ * P_STATE];            // 32 MB: Bu, then xs (in place)
__device__ __half g_Ah[L_SEQ * N2];                    // 32 MB: u fp16 (persists)
__device__ __half g_W1h[N2 * H_FEAT];
__device__ __half g_W2h[H_FEAT * N2];
__device__ float2 g_a[P_STATE];
__device__ float2 g_aT[P_STATE];
__device__ float2 g_end[C_CHUNKS * P_STATE];
__device__ float2 g_carry[C_CHUNKS * P_STATE];

__device__ __forceinline__ float2 cmul(float2 a, float2 b) {
    return make_float2(a.x * b.x - a.y * b.y, a.x * b.y + a.y * b.x);
}

__device__ __forceinline__ uint32_t smem_u32(const void* p) {
    uint32_t a;
    asm("{ .reg .u64 t; cvta.to.shared.u64 t, %1; cvt.u32.u64 %0, t; }"
        : "=r"(a) : "l"(p));
    return a;
}
__device__ __forceinline__ void cp16(uint32_t dst, const void* src) {
    asm volatile("cp.async.cg.shared.global [%0], [%1], 16;" :: "r"(dst), "l"(src));
}
__device__ __forceinline__ void ldsm4(uint32_t* r, uint32_t addr) {
    asm volatile("ldmatrix.sync.aligned.m8n8.x4.shared.b16 {%0,%1,%2,%3}, [%4];"
                 : "=r"(r[0]), "=r"(r[1]), "=r"(r[2]), "=r"(r[3]) : "r"(addr));
}
__device__ __forceinline__ void mma_f32(float* d, const uint32_t* a,
                                        uint32_t b0, uint32_t b1) {
    asm volatile(
        "mma.sync.aligned.m16n8k16.row.col.f32.f16.f16.f32 "
        "{%0,%1,%2,%3}, {%4,%5,%6,%7}, {%8,%9}, {%0,%1,%2,%3};"
        : "+f"(d[0]), "+f"(d[1]), "+f"(d[2]), "+f"(d[3])
        : "r"(a[0]), "r"(a[1]), "r"(a[2]), "r"(a[3]), "r"(b0), "r"(b1));
}

// ---------------------------------------------------------------------------
// Fused launch: blocks [0,256) build params+weights; blocks [256,1280) convert
// u fp32 -> fp16. 512 threads per block.
// ---------------------------------------------------------------------------
#define CONV_BLOCKS 1024
__global__ void __launch_bounds__(512)
prep_and_convert(const float* __restrict__ lr, const float* __restrict__ li,
                 const float* __restrict__ delta, const float* __restrict__ b,
                 const float* __restrict__ c,
                 const float4* __restrict__ u4, uint2* __restrict__ dst, int n4) {
    if (blockIdx.x < P_STATE) {
        int p = blockIdx.x;
        int h = threadIdx.x;       // 0..511
        float step = expf(delta[p]);
        float hs = 0.5f * step;
        float dr = 1.0f - hs * lr[p];
        float di = -hs * li[p];
        float inv = 1.0f / (dr * dr + di * di);
        float2 BL = make_float2(dr * inv, -di * inv);
        float2 num = make_float2(1.0f + hs * lr[p], hs * li[p]);
        float2 a = cmul(BL, num);
        float2 bs = make_float2(BL.x * step, BL.y * step);
        if (h == 0) {
            g_a[p] = a;
            float2 t = a;
            #pragma unroll
            for (int i = 0; i < SQ_POW; i++) t = cmul(t, t);
            g_aT[p] = t;
        }
        float br = b[(p * H_FEAT + h) * 2 + 0];
        float bi = b[(p * H_FEAT + h) * 2 + 1];
        g_W1h[(2 * p) * H_FEAT + h]     = __float2half_rn(bs.x * br - bs.y * bi);
        g_W1h[(2 * p + 1) * H_FEAT + h] = __float2half_rn(bs.x * bi + bs.y * br);
        g_W2h[h * N2 + 2 * p]     = __float2half_rn( 2.0f * c[(h * P_STATE + p) * 2 + 0]);
        g_W2h[h * N2 + 2 * p + 1] = __float2half_rn(-2.0f * c[(h * P_STATE + p) * 2 + 1]);
    } else {
        const int stride = CONV_BLOCKS * 512;
        for (int i = (blockIdx.x - P_STATE) * 512 + threadIdx.x; i < n4; i += stride) {
            float4 v = u4[i];
            __half2 h0 = __floats2half2_rn(v.x, v.y);
            __half2 h1 = __floats2half2_rn(v.z, v.w);
            dst[i] = make_uint2(*(uint32_t*)&h0, *(uint32_t*)&h1);
        }
    }
}

// ---------------------------------------------------------------------------
// fp16 GEMM: C[M,512] = A[M,K] x B[N,K]^T (single-rounded fp16, f32 accum)
// block 128x128, 256 thr, warp 32x64, K-chunks 32, 3-stage cp.async
// MODE 0: write half2 -> g_BuH   MODE 1: fp32 out + d*u epilogue (u fp16)
// ---------------------------------------------------------------------------
template <int MODE>
__global__ void __launch_bounds__(256, 1)
gemm_fp16(const __half* __restrict__ Ah, const __half* __restrict__ Bw,
          float* __restrict__ Cout, const __half* __restrict__ Uh,
          const float* __restrict__ D) {
    extern __shared__ char smem[];
    const uint32_t sb = smem_u32(smem);
    const int tid = threadIdx.x;
    const int wid = tid >> 5, lane = tid & 31;
    const int warpM = wid & 3, warpN = wid >> 2;       // 4x2 warp grid
    const int bm = blockIdx.y * BM;
    const int bn = blockIdx.x * BN;

    const char* baseA = (const char*)Ah + (size_t)bm * 1024;
    const char* baseB = (const char*)Bw + (size_t)bn * 1024;

    auto load_chunk = [&](int kt, int st) {
        const uint32_t base = sb + st * STG_BYTES;
        const int kb = kt * 64;                        // byte offset into row
        const int s = tid & 3;
        #pragma unroll
        for (int j = 0; j < 4; j++) {
            const int op = j >> 1;
            const int r = (tid >> 2) + ((j & 1) << 6);
            cp16(base + op * OP_BYTES + r * ROWB + s * 16,
                 (op ? baseB : baseA) + (size_t)r * 1024 + kb + s * 16);
        }
        asm volatile("cp.async.commit_group;");
    };

    load_chunk(0, 0);
    load_chunk(1, 1);

    float acc[2][8][4];
    #pragma unroll
    for (int im = 0; im < 2; im++)
        #pragma unroll
        for (int in = 0; in < 8; in++)
            #pragma unroll
            for (int q = 0; q < 4; q++) acc[im][in][q] = 0.0f;

    const uint32_t a_lo = (lane & 15) * ROWB + (lane >> 4) * 16;
    const uint32_t b_lo = ((lane & 7) + ((lane >> 4) << 3)) * ROWB +
                          ((lane >> 3) & 1) * 16;

    for (int kt = 0; kt < NCH; kt++) {
        const int st = kt % NSTAGE;
        if (kt == NCH - 1) asm volatile("cp.async.wait_group 0;");
        else               asm volatile("cp.async.wait_group 1;");
        __syncthreads();
        if (kt + 2 < NCH) load_chunk(kt + 2, (kt + 2) % NSTAGE);

        const uint32_t sg = sb + st * STG_BYTES;
        #pragma unroll
        for (int ks = 0; ks < 2; ks++) {
            const uint32_t ksb = ks * 32;
            uint32_t ah[2][4], bh[4][4];
            #pragma unroll
            for (int im = 0; im < 2; im++) {
                const uint32_t ao = (warpM * 32 + im * 16) * ROWB + a_lo + ksb;
                ldsm4(ah[im], sg + ao);
            }
            #pragma unroll
            for (int ip = 0; ip < 4; ip++) {
                const uint32_t bo = (warpN * 64 + ip * 16) * ROWB + b_lo + ksb;
                ldsm4(bh[ip], sg + OP_BYTES + bo);
            }
            #pragma unroll
            for (int im = 0; im < 2; im++)
                #pragma unroll
                for (int ip = 0; ip < 4; ip++) {
                    mma_f32(acc[im][2 * ip],     ah[im], bh[ip][0], bh[ip][1]);
                    mma_f32(acc[im][2 * ip + 1], ah[im], bh[ip][2], bh[ip][3]);
                }
        }
    }

    #pragma unroll
    for (int im = 0; im < 2; im++) {
        const int row0 = bm + warpM * 32 + im * 16 + (lane >> 2);
        #pragma unroll
        for (int in = 0; in < 8; in++) {
            const int col = bn + warpN * 64 + in * 8 + (lane & 3) * 2;
            if constexpr (MODE == 0) {
                // col is even; (col, col+1) = (re, im) of state p = col/2
                __half2 h0 = __floats2half2_rn(acc[im][in][0], acc[im][in][1]);
                __half2 h1 = __floats2half2_rn(acc[im][in][2], acc[im][in][3]);
                g_BuH[(size_t)row0 * P_STATE + (col >> 1)]       = *(uint32_t*)&h0;
                g_BuH[(size_t)(row0 + 8) * P_STATE + (col >> 1)] = *(uint32_t*)&h1;
            } else {
                float2 v0 = make_float2(acc[im][in][0], acc[im][in][1]);
                float2 v1 = make_float2(acc[im][in][2], acc[im][in][3]);
                float2 dv = *(const float2*)&D[col];
                uint32_t w0 = *(const uint32_t*)&Uh[(size_t)row0 * H_FEAT + col];
                uint32_t w1 = *(const uint32_t*)&Uh[(size_t)(row0 + 8) * H_FEAT + col];
                float2 u0 = __half22float2(*(__half2*)&w0);
                float2 u1 = __half22float2(*(__half2*)&w1);
                v0.x = fmaf(dv.x, u0.x, v0.x); v0.y = fmaf(dv.y, u0.y, v0.y);
                v1.x = fmaf(dv.x, u1.x, v1.x); v1.y = fmaf(dv.y, u1.y, v1.y);
                *(float2*)&Cout[(size_t)row0 * H_FEAT + col] = v0;
                *(float2*)&Cout[(size_t)(row0 + 8) * H_FEAT + col] = v1;
            }
        }
    }
}

// ---------------------------------------------------------------------------
// Scan stage 1: per-chunk end states only (fp16 Bu input, fp32 recurrence)
// ---------------------------------------------------------------------------
__global__ void __launch_bounds__(256) ends_kernel() {
    const int p = threadIdx.x;
    const int c = blockIdx.x;
    const float2 a = g_a[p];
    float2 x = make_float2(0.0f, 0.0f);
    size_t base = (size_t)c * T_CHUNK * P_STATE + p;
    #pragma unroll 8
    for (int t = 0; t < T_CHUNK; t++) {
        uint32_t w = g_BuH[base + (size_t)t * P_STATE];
        float2 v = __half22float2(*(__half2*)&w);
        float xr = fmaf(a.x, x.x, fmaf(-a.y, x.y, v.x));
        float xi = fmaf(a.x, x.y, fmaf(a.y, x.x, v.y));
        x = make_float2(xr, xi);
    }
    g_end[c * P_STATE + p] = x;
}

// Stage 2: Kogge-Stone inclusive scan of ends; g_carry[c] = state entering c
__global__ void __launch_bounds__(C_CHUNKS) carry_kernel() {
    __shared__ float2 s[C_CHUNKS];
    const int p = blockIdx.x;
    const int c = threadIdx.x;
    const float2 aT = g_aT[p];
    s[c] = g_end[c * P_STATE + p];
    float2 m = aT;
    __syncthreads();
    for (int d = 1; d < C_CHUNKS; d <<= 1) {
        float2 other = make_float2(0.0f, 0.0f);
        if (c >= d) other = s[c - d];
        __syncthreads();
        if (c >= d) {
            float2 cur = s[c];
            s[c] = make_float2(cur.x + m.x * other.x - m.y * other.y,
                               cur.y + m.x * other.y + m.y * other.x);
        }
        m = cmul(m, m);
        __syncthreads();
    }
    float2 ci = make_float2(0.0f, 0.0f);
    if (c > 0) ci = s[c - 1];
    g_carry[c * P_STATE + p] = ci;
}

// Stage 3: rescan with carry init; write fp16 xs IN PLACE into g_BuH
__global__ void __launch_bounds__(256) rescan_kernel() {
    const int p = threadIdx.x;
    const int c = blockIdx.x;
    const float2 a = g_a[p];
    float2 x = g_carry[c * P_STATE + p];             // state entering chunk c
    const size_t base = (size_t)c * T_CHUNK * P_STATE + p;
    #pragma unroll 4
    for (int t = 0; t < T_CHUNK; t++) {
        const size_t idx = base + (size_t)t * P_STATE;
        uint32_t w = g_BuH[idx];
        float2 v = __half22float2(*(__half2*)&w);
        float xr = fmaf(a.x, x.x, fmaf(-a.y, x.y, v.x));
        float xi = fmaf(a.x, x.y, fmaf(a.y, x.x, v.y));
        x = make_float2(xr, xi);
        __half2 h = __floats2half2_rn(x.x, x.y);
        g_BuH[idx] = *(uint32_t*)&h;                 // in-place (same thread)
    }
}

// ---------------------------------------------------------------------------
extern "C" void kernel_launch(void* const* d_in, const int* in_sizes, int n_in,
                              void* d_out, int out_size) {
    const float* u     = (const float*)d_in[0];
    const float* lr    = (const float*)d_in[1];
    const float* li    = (const float*)d_in[2];
    const float* b     = (const float*)d_in[3];
    const float* c     = (const float*)d_in[4];
    const float* d     = (const float*)d_in[5];
    const float* delta = (const float*)d_in[6];
    float* out = (float*)d_out;

    __half* ah;        cudaGetSymbolAddress((void**)&ah, g_Ah);
    __half* w1h;       cudaGetSymbolAddress((void**)&w1h, g_W1h);
    __half* w2h;       cudaGetSymbolAddress((void**)&w2h, g_W2h);
    uint32_t* buh;     cudaGetSymbolAddress((void**)&buh, g_BuH);

    cudaFuncSetAttribute(gemm_fp16<0>, cudaFuncAttributeMaxDynamicSharedMemorySize, SMEMB);
    cudaFuncSetAttribute(gemm_fp16<1>, cudaFuncAttributeMaxDynamicSharedMemorySize, SMEMB);

    const int N4 = L_SEQ * N2 / 4;

    prep_and_convert<<<P_STATE + CONV_BLOCKS, 512>>>(
        lr, li, delta, b, c, (const float4*)u, (uint2*)ah, N4);
    gemm_fp16<0><<<dim3(N2 / BN, L_SEQ / BM), 256, SMEMB>>>(
        ah, w1h, nullptr, nullptr, nullptr);
    ends_kernel<<<C_CHUNKS, P_STATE>>>();
    carry_kernel<<<P_STATE, C_CHUNKS>>>();
    rescan_kernel<<<C_CHUNKS, P_STATE>>>();
    gemm_fp16<1><<<dim3(H_FEAT / BN, L_SEQ / BM), 256, SMEMB>>>(
        (const __half*)buh, w2h, out, ah, d);
}

// round 17
// speedup vs baseline: 1.1492x; 1.0120x over previous
#include <cuda_runtime.h>
#include <cuda_fp16.h>
#include <cstdint>

// ---------------------------------------------------------------------------
// S5 SSM: ys = 2*Re( scan(Lam_bar, B_bar@u) @ C^T ) + d*u
// R17: ends+carry+rescan fused into ONE kernel with 2 software grid barriers
//      (512 blocks x 256 thr provably co-resident; counters zeroed per call).
//      GEMMs unchanged from R16 (mma.sync fp16 floor, 62.6us each).
// Pipeline: prep+convert -> gemm1 -> scan_fused -> gemm2   (4 launches)
// ---------------------------------------------------------------------------

#define L_SEQ   32768
#define H_FEAT  512
#define P_STATE 256
#define N2      512
#define C_CHUNKS 512
#define T_CHUNK  64
#define SQ_POW   6

#define BM 128
#define BN 128
#define NCH 16             // 512 / 32
#define ROWB 80            // padded smem row bytes (64B data + 16B pad)
#define OP_BYTES (128 * ROWB)          // 10240 per operand tile
#define STG_BYTES (2 * OP_BYTES)       // A, B
#define NSTAGE 3
#define SMEMB (NSTAGE * STG_BYTES)     // 61440

// Scratch (static __device__; no cudaMalloc allowed)
__device__ uint32_t g_BuH[L_SEQ * P_STATE];            // 32 MB: Bu, then xs (in place)
__device__ __half g_Ah[L_SEQ * N2];                    // 32 MB: u fp16 (persists)
__device__ __half g_W1h[N2 * H_FEAT];
__device__ __half g_W2h[H_FEAT * N2];
__device__ float2 g_a[P_STATE];
__device__ float2 g_aT[P_STATE];
__device__ float2 g_end[C_CHUNKS * P_STATE];
__device__ float2 g_carry[C_CHUNKS * P_STATE];
__device__ unsigned g_barA, g_barB;                    // grid barriers (zeroed per call)

__device__ __forceinline__ float2 cmul(float2 a, float2 b) {
    return make_float2(a.x * b.x - a.y * b.y, a.x * b.y + a.y * b.x);
}

__device__ __forceinline__ uint32_t smem_u32(const void* p) {
    uint32_t a;
    asm("{ .reg .u64 t; cvta.to.shared.u64 t, %1; cvt.u32.u64 %0, t; }"
        : "=r"(a) : "l"(p));
    return a;
}
__device__ __forceinline__ void cp16(uint32_t dst, const void* src) {
    asm volatile("cp.async.cg.shared.global [%0], [%1], 16;" :: "r"(dst), "l"(src));
}
__device__ __forceinline__ void ldsm4(uint32_t* r, uint32_t addr) {
    asm volatile("ldmatrix.sync.aligned.m8n8.x4.shared.b16 {%0,%1,%2,%3}, [%4];"
                 : "=r"(r[0]), "=r"(r[1]), "=r"(r[2]), "=r"(r[3]) : "r"(addr));
}
__device__ __forceinline__ void mma_f32(float* d, const uint32_t* a,
                                        uint32_t b0, uint32_t b1) {
    asm volatile(
        "mma.sync.aligned.m16n8k16.row.col.f32.f16.f16.f32 "
        "{%0,%1,%2,%3}, {%4,%5,%6,%7}, {%8,%9}, {%0,%1,%2,%3};"
        : "+f"(d[0]), "+f"(d[1]), "+f"(d[2]), "+f"(d[3])
        : "r"(a[0]), "r"(a[1]), "r"(a[2]), "r"(a[3]), "r"(b0), "r"(b1));
}

// Software grid barrier: safe because the whole grid is co-resident.
__device__ __forceinline__ void grid_barrier(unsigned* ctr, unsigned target) {
    __syncthreads();
    __threadfence();
    if (threadIdx.x == 0) {
        atomicAdd(ctr, 1u);
        volatile unsigned* v = (volatile unsigned*)ctr;
        while (*v < target) __nanosleep(64);
    }
    __syncthreads();
}

// ---------------------------------------------------------------------------
// Fused launch: blocks [0,256) build params+weights; blocks [256,1280) convert
// u fp32 -> fp16. 512 threads per block. Also zeroes grid-barrier counters.
// ---------------------------------------------------------------------------
#define CONV_BLOCKS 1024
__global__ void __launch_bounds__(512)
prep_and_convert(const float* __restrict__ lr, const float* __restrict__ li,
                 const float* __restrict__ delta, const float* __restrict__ b,
                 const float* __restrict__ c,
                 const float4* __restrict__ u4, uint2* __restrict__ dst, int n4) {
    if (blockIdx.x < P_STATE) {
        int p = blockIdx.x;
        int h = threadIdx.x;       // 0..511
        if (p == 0 && h == 0) { g_barA = 0; g_barB = 0; }
        float step = expf(delta[p]);
        float hs = 0.5f * step;
        float dr = 1.0f - hs * lr[p];
        float di = -hs * li[p];
        float inv = 1.0f / (dr * dr + di * di);
        float2 BL = make_float2(dr * inv, -di * inv);
        float2 num = make_float2(1.0f + hs * lr[p], hs * li[p]);
        float2 a = cmul(BL, num);
        float2 bs = make_float2(BL.x * step, BL.y * step);
        if (h == 0) {
            g_a[p] = a;
            float2 t = a;
            #pragma unroll
            for (int i = 0; i < SQ_POW; i++) t = cmul(t, t);
            g_aT[p] = t;
        }
        float br = b[(p * H_FEAT + h) * 2 + 0];
        float bi = b[(p * H_FEAT + h) * 2 + 1];
        g_W1h[(2 * p) * H_FEAT + h]     = __float2half_rn(bs.x * br - bs.y * bi);
        g_W1h[(2 * p + 1) * H_FEAT + h] = __float2half_rn(bs.x * bi + bs.y * br);
        g_W2h[h * N2 + 2 * p]     = __float2half_rn( 2.0f * c[(h * P_STATE + p) * 2 + 0]);
        g_W2h[h * N2 + 2 * p + 1] = __float2half_rn(-2.0f * c[(h * P_STATE + p) * 2 + 1]);
    } else {
        const int stride = CONV_BLOCKS * 512;
        for (int i = (blockIdx.x - P_STATE) * 512 + threadIdx.x; i < n4; i += stride) {
            float4 v = u4[i];
            __half2 h0 = __floats2half2_rn(v.x, v.y);
            __half2 h1 = __floats2half2_rn(v.z, v.w);
            dst[i] = make_uint2(*(uint32_t*)&h0, *(uint32_t*)&h1);
        }
    }
}

// ---------------------------------------------------------------------------
// fp16 GEMM: C[M,512] = A[M,K] x B[N,K]^T (single-rounded fp16, f32 accum)
// block 128x128, 256 thr, warp 32x64, K-chunks 32, 3-stage cp.async
// MODE 0: write half2 -> g_BuH   MODE 1: fp32 out + d*u epilogue (u fp16)
// ---------------------------------------------------------------------------
template <int MODE>
__global__ void __launch_bounds__(256, 1)
gemm_fp16(const __half* __restrict__ Ah, const __half* __restrict__ Bw,
          float* __restrict__ Cout, const __half* __restrict__ Uh,
          const float* __restrict__ D) {
    extern __shared__ char smem[];
    const uint32_t sb = smem_u32(smem);
    const int tid = threadIdx.x;
    const int wid = tid >> 5, lane = tid & 31;
    const int warpM = wid & 3, warpN = wid >> 2;       // 4x2 warp grid
    const int bm = blockIdx.y * BM;
    const int bn = blockIdx.x * BN;

    const char* baseA = (const char*)Ah + (size_t)bm * 1024;
    const char* baseB = (const char*)Bw + (size_t)bn * 1024;

    auto load_chunk = [&](int kt, int st) {
        const uint32_t base = sb + st * STG_BYTES;
        const int kb = kt * 64;                        // byte offset into row
        const int s = tid & 3;
        #pragma unroll
        for (int j = 0; j < 4; j++) {
            const int op = j >> 1;
            const int r = (tid >> 2) + ((j & 1) << 6);
            cp16(base + op * OP_BYTES + r * ROWB + s * 16,
                 (op ? baseB : baseA) + (size_t)r * 1024 + kb + s * 16);
        }
        asm volatile("cp.async.commit_group;");
    };

    load_chunk(0, 0);
    load_chunk(1, 1);

    float acc[2][8][4];
    #pragma unroll
    for (int im = 0; im < 2; im++)
        #pragma unroll
        for (int in = 0; in < 8; in++)
            #pragma unroll
            for (int q = 0; q < 4; q++) acc[im][in][q] = 0.0f;

    const uint32_t a_lo = (lane & 15) * ROWB + (lane >> 4) * 16;
    const uint32_t b_lo = ((lane & 7) + ((lane >> 4) << 3)) * ROWB +
                          ((lane >> 3) & 1) * 16;

    for (int kt = 0; kt < NCH; kt++) {
        const int st = kt % NSTAGE;
        if (kt == NCH - 1) asm volatile("cp.async.wait_group 0;");
        else               asm volatile("cp.async.wait_group 1;");
        __syncthreads();
        if (kt + 2 < NCH) load_chunk(kt + 2, (kt + 2) % NSTAGE);

        const uint32_t sg = sb + st * STG_BYTES;
        #pragma unroll
        for (int ks = 0; ks < 2; ks++) {
            const uint32_t ksb = ks * 32;
            uint32_t ah[2][4], bh[4][4];
            #pragma unroll
            for (int im = 0; im < 2; im++) {
                const uint32_t ao = (warpM * 32 + im * 16) * ROWB + a_lo + ksb;
                ldsm4(ah[im], sg + ao);
            }
            #pragma unroll
            for (int ip = 0; ip < 4; ip++) {
                const uint32_t bo = (warpN * 64 + ip * 16) * ROWB + b_lo + ksb;
                ldsm4(bh[ip], sg + OP_BYTES + bo);
            }
            #pragma unroll
            for (int im = 0; im < 2; im++)
                #pragma unroll
                for (int ip = 0; ip < 4; ip++) {
                    mma_f32(acc[im][2 * ip],     ah[im], bh[ip][0], bh[ip][1]);
                    mma_f32(acc[im][2 * ip + 1], ah[im], bh[ip][2], bh[ip][3]);
                }
        }
    }

    #pragma unroll
    for (int im = 0; im < 2; im++) {
        const int row0 = bm + warpM * 32 + im * 16 + (lane >> 2);
        #pragma unroll
        for (int in = 0; in < 8; in++) {
            const int col = bn + warpN * 64 + in * 8 + (lane & 3) * 2;
            if constexpr (MODE == 0) {
                __half2 h0 = __floats2half2_rn(acc[im][in][0], acc[im][in][1]);
                __half2 h1 = __floats2half2_rn(acc[im][in][2], acc[im][in][3]);
                g_BuH[(size_t)row0 * P_STATE + (col >> 1)]       = *(uint32_t*)&h0;
                g_BuH[(size_t)(row0 + 8) * P_STATE + (col >> 1)] = *(uint32_t*)&h1;
            } else {
                float2 v0 = make_float2(acc[im][in][0], acc[im][in][1]);
                float2 v1 = make_float2(acc[im][in][2], acc[im][in][3]);
                float2 dv = *(const float2*)&D[col];
                uint32_t w0 = *(const uint32_t*)&Uh[(size_t)row0 * H_FEAT + col];
                uint32_t w1 = *(const uint32_t*)&Uh[(size_t)(row0 + 8) * H_FEAT + col];
                float2 u0 = __half22float2(*(__half2*)&w0);
                float2 u1 = __half22float2(*(__half2*)&w1);
                v0.x = fmaf(dv.x, u0.x, v0.x); v0.y = fmaf(dv.y, u0.y, v0.y);
                v1.x = fmaf(dv.x, u1.x, v1.x); v1.y = fmaf(dv.y, u1.y, v1.y);
                *(float2*)&Cout[(size_t)row0 * H_FEAT + col] = v0;
                *(float2*)&Cout[(size_t)(row0 + 8) * H_FEAT + col] = v1;
            }
        }
    }
}

// ---------------------------------------------------------------------------
// Fused scan: phase A ends -> grid barrier -> phase B carry (blocks <256)
//             -> grid barrier -> phase C in-place rescan.
// 512 blocks x 256 threads: co-resident by construction (low regs/smem).
// ---------------------------------------------------------------------------
__global__ void __launch_bounds__(256)
scan_fused() {
    __shared__ float2 s[P_STATE];      // phase B pair-scan buffer (2KB)
    const int tid = threadIdx.x;
    const int blk = blockIdx.x;

    // ---- Phase A: chunk-local end states (identical math to R16 ends) ----
    {
        const int p = tid;
        const int c = blk;
        const float2 a = g_a[p];
        float2 x = make_float2(0.0f, 0.0f);
        size_t base = (size_t)c * T_CHUNK * P_STATE + p;
        #pragma unroll 8
        for (int t = 0; t < T_CHUNK; t++) {
            uint32_t w = g_BuH[base + (size_t)t * P_STATE];
            float2 v = __half22float2(*(__half2*)&w);
            float xr = fmaf(a.x, x.x, fmaf(-a.y, x.y, v.x));
            float xi = fmaf(a.x, x.y, fmaf(a.y, x.x, v.y));
            x = make_float2(xr, xi);
        }
        g_end[c * P_STATE + p] = x;
    }

    grid_barrier(&g_barA, C_CHUNKS);

    // ---- Phase B: carry scan over chunk ends (blocks 0..255, one per p) ----
    if (blk < P_STATE) {
        const int p = blk;
        const float2 aT = g_aT[p];
        // pair compression: thread t owns chunks (2t, 2t+1)
        float2 ea = g_end[(2 * tid) * P_STATE + p];
        float2 eb = g_end[(2 * tid + 1) * P_STATE + p];
        float2 t1 = cmul(aT, ea);
        s[tid] = make_float2(t1.x + eb.x, t1.y + eb.y);    // pair end
        float2 m = cmul(aT, aT);                            // pair multiplier
        __syncthreads();
        for (int d = 1; d < P_STATE; d <<= 1) {
            float2 other = make_float2(0.0f, 0.0f);
            if (tid >= d) other = s[tid - d];
            __syncthreads();
            if (tid >= d) {
                float2 cur = s[tid];
                s[tid] = make_float2(cur.x + m.x * other.x - m.y * other.y,
                                     cur.y + m.x * other.y + m.y * other.x);
            }
            m = cmul(m, m);
            __syncthreads();
        }
        float2 c0 = make_float2(0.0f, 0.0f);               // carry into chunk 2t
        if (tid > 0) c0 = s[tid - 1];
        float2 tc = cmul(aT, c0);
        float2 c1 = make_float2(tc.x + ea.x, tc.y + ea.y); // carry into chunk 2t+1
        g_carry[(2 * tid) * P_STATE + p]     = c0;
        g_carry[(2 * tid + 1) * P_STATE + p] = c1;
    }

    grid_barrier(&g_barB, C_CHUNKS);

    // ---- Phase C: rescan with carry init; in-place fp16 xs into g_BuH ----
    {
        const int p = tid;
        const int c = blk;
        const float2 a = g_a[p];
        float2 x = g_carry[c * P_STATE + p];
        const size_t base = (size_t)c * T_CHUNK * P_STATE + p;
        #pragma unroll 4
        for (int t = 0; t < T_CHUNK; t++) {
            const size_t idx = base + (size_t)t * P_STATE;
            uint32_t w = g_BuH[idx];
            float2 v = __half22float2(*(__half2*)&w);
            float xr = fmaf(a.x, x.x, fmaf(-a.y, x.y, v.x));
            float xi = fmaf(a.x, x.y, fmaf(a.y, x.x, v.y));
            x = make_float2(xr, xi);
            __half2 h = __floats2half2_rn(x.x, x.y);
            g_BuH[idx] = *(uint32_t*)&h;
        }
    }
}

// ---------------------------------------------------------------------------
extern "C" void kernel_launch(void* const* d_in, const int* in_sizes, int n_in,
                              void* d_out, int out_size) {
    const float* u     = (const float*)d_in[0];
    const float* lr    = (const float*)d_in[1];
    const float* li    = (const float*)d_in[2];
    const float* b     = (const float*)d_in[3];
    const float* c     = (const float*)d_in[4];
    const float* d     = (const float*)d_in[5];
    const float* delta = (const float*)d_in[6];
    float* out = (float*)d_out;

    __half* ah;        cudaGetSymbolAddress((void**)&ah, g_Ah);
    __half* w1h;       cudaGetSymbolAddress((void**)&w1h, g_W1h);
    __half* w2h;       cudaGetSymbolAddress((void**)&w2h, g_W2h);
    uint32_t* buh;     cudaGetSymbolAddress((void**)&buh, g_BuH);

    cudaFuncSetAttribute(gemm_fp16<0>, cudaFuncAttributeMaxDynamicSharedMemorySize, SMEMB);
    cudaFuncSetAttribute(gemm_fp16<1>, cudaFuncAttributeMaxDynamicSharedMemorySize, SMEMB);

    const int N4 = L_SEQ * N2 / 4;

    prep_and_convert<<<P_STATE + CONV_BLOCKS, 512>>>(
        lr, li, delta, b, c, (const float4*)u, (uint2*)ah, N4);
    gemm_fp16<0><<<dim3(N2 / BN, L_SEQ / BM), 256, SMEMB>>>(
        ah, w1h, nullptr, nullptr, nullptr);
    scan_fused<<<C_CHUNKS, P_STATE>>>();
    gemm_fp16<1><<<dim3(H_FEAT / BN, L_SEQ / BM), 256, SMEMB>>>(
        (const __half*)buh, w2h, out, ah, d);
}